// round 11
// baseline (speedup 1.0000x reference)
#include <cuda_runtime.h>

// Problem constants
constexpr int B = 256;
constexpr int T = 2048;
constexpr int D = 64;     // input dim
constexpr int H = 25;     // LSTM units
constexpr int G = 100;    // 4 gates * H
constexpr long long ROWS = (long long)B * T;   // 524288

// Scratch for layer-1 input projections: [B*T][25 units][4 gates] floats (~210 MB)
__device__ float g_xp[52428800];

// Packed fp32x2 FMA (2 fp32 MACs per issue, full precision)
__device__ __forceinline__ float2 ffma2(float2 a, float2 b, float2 c) {
    float2 d;
    asm("fma.rn.f32x2 %0, %1, %2, %3;"
        : "=l"(reinterpret_cast<unsigned long long &>(d))
        : "l"(reinterpret_cast<unsigned long long &>(a)),
          "l"(reinterpret_cast<unsigned long long &>(b)),
          "l"(reinterpret_cast<unsigned long long &>(c)));
    return d;
}

__device__ __forceinline__ float rcp_f(float x) {
    float r; asm("rcp.approx.f32 %0, %1;" : "=f"(r) : "f"(x)); return r;
}
__device__ __forceinline__ float sigm(float x)  { return rcp_f(1.0f + __expf(-x)); }
__device__ __forceinline__ float tanh_f(float x){ return fmaf(2.0f, rcp_f(1.0f + __expf(-2.0f * x)), -1.0f); }

// ---------------------------------------------------------------------------
// Kernel 1: layer-1 input projections.  g_xp[row][u*4+g] = x[row]·Wx_g[:,u]+b_g[u]
// Output staged in smem and copied out as contiguous float4 (coalesced).
// Static smem: pool(6400) + xT(64*68) = 43KB. sOut reuses pool after compute.
// ---------------------------------------------------------------------------
constexpr int XROWS = 64;

__global__ __launch_bounds__(256) void xproj_kernel(
    const float* __restrict__ x,
    const float* __restrict__ Wxi, const float* __restrict__ bi,
    const float* __restrict__ Wxf, const float* __restrict__ bf,
    const float* __restrict__ Wxc, const float* __restrict__ bc,
    const float* __restrict__ Wxo, const float* __restrict__ bo)
{
    __shared__ __align__(16) float pool[D * G];    // Ws during compute; sOut after
    __shared__ __align__(16) float xT[D][68];      // transposed x tile

    const int tid = threadIdx.x;
    const long long row0 = (long long)blockIdx.x * XROWS;

    // Stage combined gate weights [j][c] (c = g*25+u)
    for (int idx = tid; idx < D * G; idx += 256) {
        int j = idx / G, c = idx % G;
        int g = c / H, u = c % H;
        const float* W = (g == 0) ? Wxi : (g == 1) ? Wxf : (g == 2) ? Wxc : Wxo;
        pool[idx] = W[j * H + u];
    }
    // Stage x tile transposed (coalesced float4 loads)
    for (int idx = tid; idx < XROWS * 16; idx += 256) {
        int r = idx >> 4, jq = idx & 15;
        float4 v = *reinterpret_cast<const float4*>(&x[(row0 + r) * D + jq * 4]);
        xT[jq * 4 + 0][r] = v.x;
        xT[jq * 4 + 1][r] = v.y;
        xT[jq * 4 + 2][r] = v.z;
        xT[jq * 4 + 3][r] = v.w;
    }
    __syncthreads();

    float2 acc[16];
    int c = 0, rg = 0, u = 0, g = 0;
    if (tid < 200) {
        c  = tid % G;
        rg = tid / G;                 // row-half: 32 rows each
        g = c / H; u = c % H;
        const float bias = ((g == 0) ? bi : (g == 1) ? bf : (g == 2) ? bc : bo)[u];

        #pragma unroll
        for (int k = 0; k < 16; k++) acc[k] = make_float2(bias, bias);

        #pragma unroll 4
        for (int j = 0; j < D; j++) {
            float w = pool[j * G + c];
            float2 wp = make_float2(w, w);
            #pragma unroll
            for (int k4 = 0; k4 < 8; k4++) {       // broadcast LDS.128, 4 rows each
                float4 x4 = *reinterpret_cast<const float4*>(&xT[j][rg * 32 + k4 * 4]);
                acc[2 * k4]     = ffma2(make_float2(x4.x, x4.y), wp, acc[2 * k4]);
                acc[2 * k4 + 1] = ffma2(make_float2(x4.z, x4.w), wp, acc[2 * k4 + 1]);
            }
        }
    }
    __syncthreads();     // all reads of pool/xT complete; reuse pool as sOut

    if (tid < 200) {
        const int col = u * 4 + g;
        #pragma unroll
        for (int k = 0; k < 16; k++) {
            pool[(rg * 32 + 2 * k)     * G + col] = acc[k].x;
            pool[(rg * 32 + 2 * k + 1) * G + col] = acc[k].y;
        }
    }
    __syncthreads();

    // Coalesced copy-out: 6400 floats = 1600 float4, contiguous in g_xp
    const float4* src = reinterpret_cast<const float4*>(pool);
    float4* dst = reinterpret_cast<float4*>(&g_xp[row0 * G]);
    for (int i = tid; i < 1600; i += 256) dst[i] = src[i];
}

// ---------------------------------------------------------------------------
// Kernel 2: barrier-free fused recurrence. One WARP per batch element.
// Lane u<25 owns unit u of both layers. Per iteration t:
//   L1:  h1_t     = f(h1_{t-1} [smem], xg_t [prefetched])     wh1 in REGISTERS
//   L2:  h2_{t-1} = f(h1_{t-1} [same smem read], h2_{t-2})    wx2+wh2 in SMEM
//   OUT: y_{t-1}  = sigm(h2_{t-1}·Wout + b)  via shfl reduce
// L2 bias folded into wx2's j=25 slot with h1[25]:=1.
// Weight smem layout [r][u] float4 (r = g*7+jq): lane-indexed LDS.128 is
// conflict-free (8-lane phases span contiguous 128B). Registers ~175, NO SPILLS.
// Block = 64 threads (2 elements, warps on separate SMSPs); grid = 128.
// ---------------------------------------------------------------------------
struct __align__(16) ElemS {
    float h1[2][28];   // [parity][unit]; [25]=1.0 (bias lane), [26..27]=0
    float h2[2][28];   // [25..27]=0
};

__global__ __launch_bounds__(64, 1) void lstm_kernel(
    const float* __restrict__ Whi1, const float* __restrict__ Whf1,
    const float* __restrict__ Whc1, const float* __restrict__ Who1,
    const float* __restrict__ Wxi2, const float* __restrict__ Wxf2,
    const float* __restrict__ Wxc2, const float* __restrict__ Wxo2,
    const float* __restrict__ bi2,  const float* __restrict__ bf2,
    const float* __restrict__ bc2,  const float* __restrict__ bo2,
    const float* __restrict__ Whi2, const float* __restrict__ Whf2,
    const float* __restrict__ Whc2, const float* __restrict__ Who2,
    const float* __restrict__ Wout, const float* __restrict__ bout,
    float* __restrict__ out)
{
    __shared__ ElemS se[2];
    __shared__ __align__(16) float4 wxs[28][25];   // [g*7+jq][u]: wx2 (+bias at j=25)
    __shared__ __align__(16) float4 w2s[28][25];   // [g*7+jq][u]: wh2

    const int tid  = threadIdx.x;
    const int wid  = tid >> 5;          // element within block
    const int lane = tid & 31;
    const int uu   = (lane < 25) ? lane : 24;
    const long long bT = (long long)(blockIdx.x * 2 + wid) * T;

    // ---- cooperative init: weights into smem, zero h buffers ----
    for (int idx = tid; idx < 28 * 25; idx += 64) {
        int r = idx / 25, u = idx % 25, g = r / 7, jq = r % 7, j0 = jq * 4;
        const float* WX = (g == 0) ? Wxi2 : (g == 1) ? Wxf2 : (g == 2) ? Wxc2 : Wxo2;
        const float* BB = (g == 0) ? bi2  : (g == 1) ? bf2  : (g == 2) ? bc2  : bo2;
        const float* W2 = (g == 0) ? Whi2 : (g == 1) ? Whf2 : (g == 2) ? Whc2 : Who2;
        float4 v, w;
        v.x = (j0     < 25) ? WX[(j0)     * 25 + u] : 0.f;
        v.y = (j0 + 1 < 25) ? WX[(j0 + 1) * 25 + u] : ((j0 + 1 == 25) ? BB[u] : 0.f);
        v.z = (j0 + 2 < 25) ? WX[(j0 + 2) * 25 + u] : 0.f;
        v.w = (j0 + 3 < 25) ? WX[(j0 + 3) * 25 + u] : 0.f;
        w.x = (j0     < 25) ? W2[(j0)     * 25 + u] : 0.f;
        w.y = (j0 + 1 < 25) ? W2[(j0 + 1) * 25 + u] : 0.f;
        w.z = (j0 + 2 < 25) ? W2[(j0 + 2) * 25 + u] : 0.f;
        w.w = (j0 + 3 < 25) ? W2[(j0 + 3) * 25 + u] : 0.f;
        wxs[r][u] = v;
        w2s[r][u] = w;
    }
    {
        float* sz = reinterpret_cast<float*>(se);
        for (int i = tid; i < (int)(2 * sizeof(ElemS) / 4); i += 64) sz[i] = 0.f;
    }
    __syncthreads();
    if (tid < 2) { se[tid].h1[0][25] = 1.0f; se[tid].h1[1][25] = 1.0f; }
    __syncthreads();

    // ---- per-lane register weights: L1 recurrent only (critical path) ----
    float2 wh1[4][13];
    #pragma unroll
    for (int g = 0; g < 4; g++) {
        const float* W1 = (g == 0) ? Whi1 : (g == 1) ? Whf1 : (g == 2) ? Whc1 : Who1;
        #pragma unroll
        for (int jp = 0; jp < 13; jp++) {
            int j0 = 2 * jp, j1 = 2 * jp + 1;
            wh1[g][jp].x = W1[j0 * 25 + uu];
            wh1[g][jp].y = (j1 < 25) ? W1[j1 * 25 + uu] : 0.f;
        }
    }
    const float wout_u = (lane < 25) ? Wout[lane] : 0.f;
    const float boV = bout[0];

    const float4* h1b[2] = { reinterpret_cast<const float4*>(se[wid].h1[0]),
                             reinterpret_cast<const float4*>(se[wid].h1[1]) };
    const float4* h2b[2] = { reinterpret_cast<const float4*>(se[wid].h2[0]),
                             reinterpret_cast<const float4*>(se[wid].h2[1]) };
    const float4* wxu = &wxs[0][uu];    // stride 25 float4 between rows
    const float4* w2u = &w2s[0][uu];

    float c1 = 0.f, c2 = 0.f;
    float4 q[4];
    #pragma unroll
    for (int k = 0; k < 4; k++)
        q[k] = *reinterpret_cast<const float4*>(&g_xp[(bT + k) * G + uu * 4]);

    for (int tb = 0; tb <= T; tb += 4) {
        #pragma unroll
        for (int k = 0; k < 4; k++) {
            const int t   = tb + k;
            const int pr1 = (k + 1) & 1;   // h1_{t-1}
            const int pw1 = k & 1;         // h1_t
            const int pr2 = k & 1;         // h2_{t-2}
            const int pw2 = (k + 1) & 1;   // h2_{t-1}

            float4 xg = q[k];
            if (t + 4 < T)
                q[k] = *reinterpret_cast<const float4*>(&g_xp[(bT + t + 4) * G + uu * 4]);

            float2 aL[4], aZ[4];
            #pragma unroll
            for (int g = 0; g < 4; g++) { aL[g] = make_float2(0.f, 0.f); aZ[g] = make_float2(0.f, 0.f); }

            #pragma unroll
            for (int jq = 0; jq < 7; jq++) {
                float4 h4 = h1b[pr1][jq];                       // broadcast LDS.128
                float2 p0 = make_float2(h4.x, h4.y);
                float2 p1 = make_float2(h4.z, h4.w);
                float4 g4 = h2b[pr2][jq];
                float2 r0 = make_float2(g4.x, g4.y);
                float2 r1 = make_float2(g4.z, g4.w);
                #pragma unroll
                for (int g = 0; g < 4; g++) {
                    float4 wxv = wxu[(g * 7 + jq) * 25];        // conflict-free LDS.128
                    float4 w2v = w2u[(g * 7 + jq) * 25];
                    aL[g] = ffma2(p0, wh1[g][2 * jq], aL[g]);
                    aZ[g] = ffma2(p0, make_float2(wxv.x, wxv.y), aZ[g]);
                    aZ[g] = ffma2(r0, make_float2(w2v.x, w2v.y), aZ[g]);
                    if (2 * jq + 1 < 13) {
                        aL[g] = ffma2(p1, wh1[g][2 * jq + 1], aL[g]);
                        aZ[g] = ffma2(p1, make_float2(wxv.z, wxv.w), aZ[g]);
                        aZ[g] = ffma2(r1, make_float2(w2v.z, w2v.w), aZ[g]);
                    }
                }
            }

            // ---- L1 finish: h1_t ----
            {
                float gi = sigm  (aL[0].x + aL[0].y + xg.x);
                float gf = sigm  (aL[1].x + aL[1].y + xg.y);
                float gg = tanh_f(aL[2].x + aL[2].y + xg.z);
                float go = sigm  (aL[3].x + aL[3].y + xg.w);
                float c1n = fmaf(gf, c1, gi * gg);
                if (t < T) c1 = c1n;
                float h1v = go * tanh_f(c1n);
                if (t < T && lane < 25) se[wid].h1[pw1][lane] = h1v;
            }

            // ---- L2 finish: h2_{t-1} + output y_{t-1} ----
            {
                const bool on = (t >= 1) && (t <= T);   // tail guard
                float hi = sigm  (aZ[0].x + aZ[0].y);
                float hf = sigm  (aZ[1].x + aZ[1].y);
                float hg = tanh_f(aZ[2].x + aZ[2].y);
                float ho = sigm  (aZ[3].x + aZ[3].y);
                float c2n = fmaf(hf, c2, hi * hg);
                if (on) c2 = c2n;
                float h2v = ho * tanh_f(c2n);
                if (on && lane < 25) se[wid].h2[pw2][lane] = h2v;

                float term = h2v * wout_u;
                #pragma unroll
                for (int m = 16; m > 0; m >>= 1)
                    term += __shfl_xor_sync(0xffffffffu, term, m);
                if (on && lane == 0) out[bT + (t - 1)] = sigm(term + boV);
            }

            __syncwarp();
        }
    }
}

// ---------------------------------------------------------------------------
// Host launcher. Input order detected from in_sizes (validated R3/R4/R10):
//   dict order      : x, Wout(25), bout(1), l1_*(12), l2_*(12)
//   signature order : x, l1_*(12), l2_*(12), Wout, bout
// Per-layer order: Wxi, bi, Whi, Wxf, bf, Whf, Wxc, bc, Whc, Wxo, bo, Who
// ---------------------------------------------------------------------------
extern "C" void kernel_launch(void* const* d_in, const int* in_sizes, int n_in,
                              void* d_out, int out_size) {
    const float* p[27];
    for (int i = 0; i < 27 && i < n_in; i++) p[i] = (const float*)d_in[i];
    const float* x = p[0];

    int l1, l2, iWout, ibout;
    if (n_in >= 3 && in_sizes[1] == H) {   // dict order (Wout right after x)
        iWout = 1; ibout = 2; l1 = 3; l2 = 15;
    } else {                                // reference-signature order
        l1 = 1; l2 = 13; iWout = 25; ibout = 26;
    }

    xproj_kernel<<<(int)(ROWS / XROWS), 256>>>(
        x,
        p[l1 + 0], p[l1 + 1],    // Wxi, bi
        p[l1 + 3], p[l1 + 4],    // Wxf, bf
        p[l1 + 6], p[l1 + 7],    // Wxc, bc
        p[l1 + 9], p[l1 + 10]);  // Wxo, bo

    lstm_kernel<<<B / 2, 64>>>(
        p[l1 + 2], p[l1 + 5], p[l1 + 8], p[l1 + 11],     // l1 Whi, Whf, Whc, Who
        p[l2 + 0], p[l2 + 3], p[l2 + 6], p[l2 + 9],      // l2 Wxi, Wxf, Wxc, Wxo
        p[l2 + 1], p[l2 + 4], p[l2 + 7], p[l2 + 10],     // l2 bi, bf, bc, bo
        p[l2 + 2], p[l2 + 5], p[l2 + 8], p[l2 + 11],     // l2 Whi, Whf, Whc, Who
        p[iWout], p[ibout],
        (float*)d_out);
}

// round 12
// speedup vs baseline: 1.2613x; 1.2613x over previous
#include <cuda_runtime.h>

// Problem constants
constexpr int B = 256;
constexpr int T = 2048;
constexpr int D = 64;     // input dim
constexpr int H = 25;     // LSTM units
constexpr int G = 100;    // 4 gates * H
constexpr long long ROWS = (long long)B * T;   // 524288

// Scratch for layer-1 input projections: [B*T][25 units][4 gates] floats (~210 MB)
__device__ float g_xp[52428800];

// Packed fp32x2 FMA
__device__ __forceinline__ float2 ffma2(float2 a, float2 b, float2 c) {
    float2 d;
    asm("fma.rn.f32x2 %0, %1, %2, %3;"
        : "=l"(reinterpret_cast<unsigned long long &>(d))
        : "l"(reinterpret_cast<unsigned long long &>(a)),
          "l"(reinterpret_cast<unsigned long long &>(b)),
          "l"(reinterpret_cast<unsigned long long &>(c)));
    return d;
}

__device__ __forceinline__ float rcp_f(float x) {
    float r; asm("rcp.approx.f32 %0, %1;" : "=f"(r) : "f"(x)); return r;
}
__device__ __forceinline__ float sigm(float x)  { return rcp_f(1.0f + __expf(-x)); }
__device__ __forceinline__ float tanh_f(float x){ return fmaf(2.0f, rcp_f(1.0f + __expf(-2.0f * x)), -1.0f); }

// ---------------------------------------------------------------------------
// Kernel 1: layer-1 input projections (R10 variant — measured faster than R11).
// g_xp[row][u*4+g] = x[row]·Wx_g[:,u] + b_g[u]
// ---------------------------------------------------------------------------
constexpr int XROWS = 64;

__global__ __launch_bounds__(256) void xproj_kernel(
    const float* __restrict__ x,
    const float* __restrict__ Wxi, const float* __restrict__ bi,
    const float* __restrict__ Wxf, const float* __restrict__ bf,
    const float* __restrict__ Wxc, const float* __restrict__ bc,
    const float* __restrict__ Wxo, const float* __restrict__ bo)
{
    __shared__ __align__(16) float Ws[D * G];      // weights, [j][c] (c = g*25+u)
    __shared__ __align__(16) float xT[D][68];      // transposed x tile

    const int tid = threadIdx.x;
    const long long row0 = (long long)blockIdx.x * XROWS;

    for (int idx = tid; idx < D * G; idx += 256) {
        int j = idx / G, c = idx % G;
        int g = c / H, u = c % H;
        const float* W = (g == 0) ? Wxi : (g == 1) ? Wxf : (g == 2) ? Wxc : Wxo;
        Ws[idx] = W[j * H + u];
    }
    for (int idx = tid; idx < XROWS * 16; idx += 256) {
        int r = idx >> 4, jq = idx & 15;
        float4 v = *reinterpret_cast<const float4*>(&x[(row0 + r) * D + jq * 4]);
        xT[jq * 4 + 0][r] = v.x;
        xT[jq * 4 + 1][r] = v.y;
        xT[jq * 4 + 2][r] = v.z;
        xT[jq * 4 + 3][r] = v.w;
    }
    __syncthreads();

    if (tid < 200) {
        const int c  = tid % G;
        const int rg = tid / G;    // row-half: 32 rows each
        const int g = c / H, u = c % H;
        const float bias = ((g == 0) ? bi : (g == 1) ? bf : (g == 2) ? bc : bo)[u];

        float2 acc[16];
        #pragma unroll
        for (int k = 0; k < 16; k++) acc[k] = make_float2(0.f, 0.f);

        #pragma unroll 4
        for (int j = 0; j < D; j++) {
            float w = Ws[j * G + c];
            float2 wp = make_float2(w, w);
            #pragma unroll
            for (int k4 = 0; k4 < 8; k4++) {       // broadcast LDS.128, 4 rows each
                float4 x4 = *reinterpret_cast<const float4*>(&xT[j][rg * 32 + k4 * 4]);
                acc[2 * k4]     = ffma2(make_float2(x4.x, x4.y), wp, acc[2 * k4]);
                acc[2 * k4 + 1] = ffma2(make_float2(x4.z, x4.w), wp, acc[2 * k4 + 1]);
            }
        }

        float* outp = &g_xp[(row0 + rg * 32) * G + (u * 4 + g)];
        #pragma unroll
        for (int k = 0; k < 16; k++) {
            outp[(2 * k)     * G] = acc[k].x + bias;
            outp[(2 * k + 1) * G] = acc[k].y + bias;
        }
    }
}

// ---------------------------------------------------------------------------
// Kernel 2: fused recurrence, TWO warps per batch element, 1 barrier/step.
//   Warp A (role 0): L1 recurrence. wh1 in registers (104). Reads h1 broadcast,
//                    xg prefetched from g_xp. Writes h1_t to smem ring.
//   Warp B (role 1): L2 recurrence + head, lag 1. wx2 AND wh2 in registers
//                    (208). Reads h1/h2 broadcast only. Writes h2, out.
// Bias of L2 folded into wx2's j=25 slot; h1[25] == 1.0 permanently.
// Block = 128 threads = 2 elements -> 4 warps on 4 distinct SMSPs. Grid = 128.
// Parity double-buffering: A writes h1[t&1] after barrier t; B reads h1[(t-1)&1]
// in iteration t (separated by that barrier). Single __syncthreads suffices.
// ---------------------------------------------------------------------------
struct __align__(16) ElemS {
    float h1[2][28];   // [parity][unit]; [25]=1.0 (bias lane), [26..27]=0
    float h2[2][28];   // [25..27]=0
};

__global__ __launch_bounds__(128, 1) void lstm_kernel(
    const float* __restrict__ Whi1, const float* __restrict__ Whf1,
    const float* __restrict__ Whc1, const float* __restrict__ Who1,
    const float* __restrict__ Wxi2, const float* __restrict__ Wxf2,
    const float* __restrict__ Wxc2, const float* __restrict__ Wxo2,
    const float* __restrict__ bi2,  const float* __restrict__ bf2,
    const float* __restrict__ bc2,  const float* __restrict__ bo2,
    const float* __restrict__ Whi2, const float* __restrict__ Whf2,
    const float* __restrict__ Whc2, const float* __restrict__ Who2,
    const float* __restrict__ Wout, const float* __restrict__ bout,
    float* __restrict__ out)
{
    __shared__ ElemS se[2];

    const int tid  = threadIdx.x;
    const int wid  = tid >> 5;
    const int lane = tid & 31;
    const int uu   = (lane < 25) ? lane : 24;
    const int el   = wid >> 1;          // element within block
    const int role = wid & 1;           // 0 = A (L1), 1 = B (L2 + head)
    const long long bT = (long long)(blockIdx.x * 2 + el) * T;

    // ---- init smem ----
    {
        float* sz = reinterpret_cast<float*>(se);
        for (int i = tid; i < (int)(2 * sizeof(ElemS) / 4); i += 128) sz[i] = 0.f;
    }
    __syncthreads();
    if (tid < 2) { se[tid].h1[0][25] = 1.0f; se[tid].h1[1][25] = 1.0f; }
    __syncthreads();

    if (role == 0) {
        // ================= Warp A: layer-1 recurrence =================
        float2 wh[4][13];
        #pragma unroll
        for (int g = 0; g < 4; g++) {
            const float* W1 = (g == 0) ? Whi1 : (g == 1) ? Whf1 : (g == 2) ? Whc1 : Who1;
            #pragma unroll
            for (int jp = 0; jp < 13; jp++) {
                int j0 = 2 * jp, j1 = 2 * jp + 1;
                wh[g][jp].x = W1[j0 * 25 + uu];
                wh[g][jp].y = (j1 < 25) ? W1[j1 * 25 + uu] : 0.f;   // [12].y = 0 (pairs h1[25]=1)
            }
        }
        const float4* h1r[2] = { reinterpret_cast<const float4*>(se[el].h1[0]),
                                 reinterpret_cast<const float4*>(se[el].h1[1]) };
        float c1 = 0.f;
        float4 q[4];
        #pragma unroll
        for (int k = 0; k < 4; k++)
            q[k] = *reinterpret_cast<const float4*>(&g_xp[(bT + k) * G + uu * 4]);

        for (int t = 0; t < T + 2; t += 2) {
            #pragma unroll
            for (int k = 0; k < 2; k++) {
                const int tt = t + k;
                __syncthreads();
                if (tt < T) {
                    float4 xg = q[tt & 3];
                    if (tt + 4 < T)
                        q[tt & 3] = *reinterpret_cast<const float4*>(&g_xp[(bT + tt + 4) * G + uu * 4]);

                    const float4* hp = h1r[(tt + 1) & 1];   // h1_{t-1}
                    float2 a0 = make_float2(0.f, 0.f), a1 = a0, a2 = a0, a3 = a0;
                    #pragma unroll
                    for (int jq = 0; jq < 7; jq++) {
                        float4 h4 = hp[jq];                 // broadcast LDS.128
                        float2 p0 = make_float2(h4.x, h4.y);
                        float2 p1 = make_float2(h4.z, h4.w);
                        a0 = ffma2(p0, wh[0][2 * jq], a0);
                        a1 = ffma2(p0, wh[1][2 * jq], a1);
                        a2 = ffma2(p0, wh[2][2 * jq], a2);
                        a3 = ffma2(p0, wh[3][2 * jq], a3);
                        if (2 * jq + 1 < 13) {
                            a0 = ffma2(p1, wh[0][2 * jq + 1], a0);
                            a1 = ffma2(p1, wh[1][2 * jq + 1], a1);
                            a2 = ffma2(p1, wh[2][2 * jq + 1], a2);
                            a3 = ffma2(p1, wh[3][2 * jq + 1], a3);
                        }
                    }
                    float gi = sigm  (a0.x + a0.y + xg.x);
                    float gf = sigm  (a1.x + a1.y + xg.y);
                    float gg = tanh_f(a2.x + a2.y + xg.z);
                    float go = sigm  (a3.x + a3.y + xg.w);
                    c1 = fmaf(gf, c1, gi * gg);
                    float h1v = go * tanh_f(c1);
                    if (lane < 25) se[el].h1[tt & 1][lane] = h1v;
                }
            }
        }
    } else {
        // ================= Warp B: layer-2 recurrence + head =================
        float2 wx[4][13], wh[4][13];   // wx[g][12].y = bias (pairs h1[25]=1)
        #pragma unroll
        for (int g = 0; g < 4; g++) {
            const float* WX = (g == 0) ? Wxi2 : (g == 1) ? Wxf2 : (g == 2) ? Wxc2 : Wxo2;
            const float* BB = (g == 0) ? bi2  : (g == 1) ? bf2  : (g == 2) ? bc2  : bo2;
            const float* W2 = (g == 0) ? Whi2 : (g == 1) ? Whf2 : (g == 2) ? Whc2 : Who2;
            #pragma unroll
            for (int jp = 0; jp < 13; jp++) {
                int j0 = 2 * jp, j1 = 2 * jp + 1;
                wx[g][jp].x = WX[j0 * 25 + uu];
                wx[g][jp].y = (j1 < 25) ? WX[j1 * 25 + uu] : ((j1 == 25) ? BB[uu] : 0.f);
                wh[g][jp].x = W2[j0 * 25 + uu];
                wh[g][jp].y = (j1 < 25) ? W2[j1 * 25 + uu] : 0.f;
            }
        }
        const float wout_u = (lane < 25) ? Wout[lane] : 0.f;
        const float boV = bout[0];
        const float4* h1r[2] = { reinterpret_cast<const float4*>(se[el].h1[0]),
                                 reinterpret_cast<const float4*>(se[el].h1[1]) };
        const float4* h2r[2] = { reinterpret_cast<const float4*>(se[el].h2[0]),
                                 reinterpret_cast<const float4*>(se[el].h2[1]) };
        float c2 = 0.f;

        for (int t = 0; t < T + 2; t += 2) {
            #pragma unroll
            for (int k = 0; k < 2; k++) {
                const int tt = t + k;
                __syncthreads();
                if (tt >= 1 && tt <= T) {
                    const int s = tt - 1;
                    const float4* hp = h1r[s & 1];          // h1_s (written by A at iter s)
                    const float4* gp = h2r[(s + 1) & 1];    // h2_{s-1} (own, prev iter)
                    float2 z0 = make_float2(0.f, 0.f), z1 = z0, z2 = z0, z3 = z0;
                    #pragma unroll
                    for (int jq = 0; jq < 7; jq++) {
                        float4 h4 = hp[jq];                 // broadcast LDS.128
                        float4 g4 = gp[jq];
                        float2 p0 = make_float2(h4.x, h4.y);
                        float2 p1 = make_float2(h4.z, h4.w);
                        float2 r0 = make_float2(g4.x, g4.y);
                        float2 r1 = make_float2(g4.z, g4.w);
                        z0 = ffma2(p0, wx[0][2 * jq], z0);  z0 = ffma2(r0, wh[0][2 * jq], z0);
                        z1 = ffma2(p0, wx[1][2 * jq], z1);  z1 = ffma2(r0, wh[1][2 * jq], z1);
                        z2 = ffma2(p0, wx[2][2 * jq], z2);  z2 = ffma2(r0, wh[2][2 * jq], z2);
                        z3 = ffma2(p0, wx[3][2 * jq], z3);  z3 = ffma2(r0, wh[3][2 * jq], z3);
                        if (2 * jq + 1 < 13) {
                            z0 = ffma2(p1, wx[0][2 * jq + 1], z0);  z0 = ffma2(r1, wh[0][2 * jq + 1], z0);
                            z1 = ffma2(p1, wx[1][2 * jq + 1], z1);  z1 = ffma2(r1, wh[1][2 * jq + 1], z1);
                            z2 = ffma2(p1, wx[2][2 * jq + 1], z2);  z2 = ffma2(r1, wh[2][2 * jq + 1], z2);
                            z3 = ffma2(p1, wx[3][2 * jq + 1], z3);  z3 = ffma2(r1, wh[3][2 * jq + 1], z3);
                        }
                    }
                    float hi = sigm  (z0.x + z0.y);
                    float hf = sigm  (z1.x + z1.y);
                    float hg = tanh_f(z2.x + z2.y);
                    float ho = sigm  (z3.x + z3.y);
                    c2 = fmaf(hf, c2, hi * hg);
                    float h2v = ho * tanh_f(c2);
                    if (lane < 25) se[el].h2[s & 1][lane] = h2v;

                    float term = h2v * wout_u;
                    #pragma unroll
                    for (int m = 16; m > 0; m >>= 1)
                        term += __shfl_xor_sync(0xffffffffu, term, m);
                    if (lane == 0) out[bT + s] = sigm(term + boV);
                }
            }
        }
    }
}

// ---------------------------------------------------------------------------
// Host launcher. Input order detected from in_sizes (validated R3..R11):
//   dict order      : x, Wout(25), bout(1), l1_*(12), l2_*(12)
//   signature order : x, l1_*(12), l2_*(12), Wout, bout
// Per-layer order: Wxi, bi, Whi, Wxf, bf, Whf, Wxc, bc, Whc, Wxo, bo, Who
// ---------------------------------------------------------------------------
extern "C" void kernel_launch(void* const* d_in, const int* in_sizes, int n_in,
                              void* d_out, int out_size) {
    const float* p[27];
    for (int i = 0; i < 27 && i < n_in; i++) p[i] = (const float*)d_in[i];
    const float* x = p[0];

    int l1, l2, iWout, ibout;
    if (n_in >= 3 && in_sizes[1] == H) {   // dict order (Wout right after x)
        iWout = 1; ibout = 2; l1 = 3; l2 = 15;
    } else {                                // reference-signature order
        l1 = 1; l2 = 13; iWout = 25; ibout = 26;
    }

    xproj_kernel<<<(int)(ROWS / XROWS), 256>>>(
        x,
        p[l1 + 0], p[l1 + 1],    // Wxi, bi
        p[l1 + 3], p[l1 + 4],    // Wxf, bf
        p[l1 + 6], p[l1 + 7],    // Wxc, bc
        p[l1 + 9], p[l1 + 10]);  // Wxo, bo

    lstm_kernel<<<B / 2, 128>>>(
        p[l1 + 2], p[l1 + 5], p[l1 + 8], p[l1 + 11],     // l1 Whi, Whf, Whc, Who
        p[l2 + 0], p[l2 + 3], p[l2 + 6], p[l2 + 9],      // l2 Wxi, Wxf, Wxc, Wxo
        p[l2 + 1], p[l2 + 4], p[l2 + 7], p[l2 + 10],     // l2 bi, bf, bc, bo
        p[l2 + 2], p[l2 + 5], p[l2 + 8], p[l2 + 11],     // l2 Whi, Whf, Whc, Who
        p[iWout], p[ibout],
        (float*)d_out);
}